// round 16
// baseline (speedup 1.0000x reference)
#include <cuda_runtime.h>

#define BB 4096
#define PP 128
#define GG 128

#define SCX (8000.0f / 79.0f)
#define SCY (8000.0f / 79.0f)
#define SCZ (2000.0f / 19.0f)
#define BX (-4000.0f)
#define BY (-4000.0f)
#define BZ (0.0f)

#define DIST_THRESH_SQ (500.0f * 500.0f)
#define BBOX_THRESH 0.1f
#define EOFF 2.0e8f              // keeps e strictly positive for all finite inputs
#define KEYMASK (~31)            // drop low 5 float bits, embed q (q < 32)

typedef unsigned long long ull;

// ---- packed f32x2 helpers (sm_103a) ----
__device__ __forceinline__ ull pack2(float lo, float hi) {
    ull r;
    asm("mov.b64 %0, {%1, %2};" : "=l"(r) : "f"(lo), "f"(hi));
    return r;
}
__device__ __forceinline__ void unpack2(ull v, float& lo, float& hi) {
    asm("mov.b64 {%0, %1}, %2;" : "=f"(lo), "=f"(hi) : "l"(v));
}
__device__ __forceinline__ ull fma2(ull a, ull b, ull c) {
    ull r;
    asm("fma.rn.f32x2 %0, %1, %2, %3;" : "=l"(r) : "l"(a), "l"(b), "l"(c));
    return r;
}
// (bits(s) & KEYMASK) | q in a single LOP3
__device__ __forceinline__ int keyfuse(float s, int q) {
    int r;
    asm("lop3.b32 %0, %1, %2, %3, 0xea;"   // (a & b) | c
        : "=r"(r) : "r"(__float_as_int(s)), "n"(KEYMASK), "r"(q));
    return r;
}

__global__ __launch_bounds__(PP, 12)   // cap regs ~40 -> 12 CTAs/SM possible
void proposal_layer_kernel(const int*   __restrict__ topk_index,      // [B,P,3]
                           const float* __restrict__ topk_confs,      // [B,P]
                           const float* __restrict__ match_bbox_preds,// [B,P,2]
                           const float* __restrict__ roots_3d,        // [B,G,3]
                           const float* __restrict__ gt_bbox,         // [B,G,2]
                           const int*   __restrict__ num_person,      // [B]
                           float*       __restrict__ out)             // [B,P,7]
{
    const int b = blockIdx.x;
    const int t = threadIdx.x;  // 0..127, one proposal per thread

    __shared__ __align__(16) float s_nx[GG];   // -rx
    __shared__ __align__(16) float s_ny[GG];   // -ry
    __shared__ __align__(16) float s_nz[GG];   // -rz
    __shared__ __align__(16) float s_h [GG];   // |r|^2/2 + EOFF, +INF for g >= n
    __shared__ __align__(16) float4 s_out4[224];

    const int n = num_person[b];  // uniform, broadcast

    // ---- stage gt roots; pad h with +INF past n (no tail loop) ----
    {
        const float* r = roots_3d + ((size_t)b * GG + t) * 3;
        float rx = r[0], ry = r[1], rz = r[2];
        s_nx[t] = -rx;
        s_ny[t] = -ry;
        s_nz[t] = -rz;
        float hv = __fmaf_rn(0.5f, __fmaf_rn(rz, rz, __fmaf_rn(ry, ry, rx * rx)), EOFF);
        s_h[t]  = (t < n) ? hv : __int_as_float(0x7F800000);
    }
    __syncthreads();

    // ---- proposal coords only (conf/match/bbox deferred past the scan) ----
    const int* ti = topk_index + ((size_t)b * PP + t) * 3;
    const float cx = (float)ti[0] * SCX + BX;
    const float cy = (float)ti[1] * SCY + BY;
    const float cz = (float)ti[2] * SCZ + BZ;

    const ull cxx = pack2(cx, cx);
    const ull cyy = pack2(cy, cy);
    const ull czz = pack2(cz, cz);

    const ulonglong2* px = (const ulonglong2*)s_nx;
    const ulonglong2* py = (const ulonglong2*)s_ny;
    const ulonglong2* pz = (const ulonglong2*)s_nz;
    const ulonglong2* ph = (const ulonglong2*)s_h;

    // ---- scan: 4 int-key chains; key = (bits(e)&~31) | q, IMNMX update ----
    int bk0 = 0x7FFFFFFF, bk1 = 0x7FFFFFFF, bk2 = 0x7FFFFFFF, bk3 = 0x7FFFFFFF;

    const int nbc = (n + 3) >> 2;   // ceil(n/4); INF pads never win
    #pragma unroll 2
    for (int q = 0; q < nbc; ++q) {
        ulonglong2 X = px[q];   // LDS.128 broadcast
        ulonglong2 Y = py[q];
        ulonglong2 Z = pz[q];
        ulonglong2 H = ph[q];

        ull eA = fma2(cxx, X.x, fma2(cyy, Y.x, fma2(czz, Z.x, H.x)));
        ull eB = fma2(cxx, X.y, fma2(cyy, Y.y, fma2(czz, Z.y, H.y)));
        float s0, s1, s2, s3;
        unpack2(eA, s0, s1);
        unpack2(eB, s2, s3);

        bk0 = min(bk0, keyfuse(s0, q));   // LOP3 + IMNMX per element
        bk1 = min(bk1, keyfuse(s1, q));
        bk2 = min(bk2, keyfuse(s2, q));
        bk3 = min(bk3, keyfuse(s3, q));
    }

    // ---- merge chains: masked values, strict < (residue order = g order) ----
    int best_mv = bk0 & KEYMASK;
    int bi = ((bk0 & 31) << 2);
    { int mv = bk1 & KEYMASK; if (mv < best_mv) { best_mv = mv; bi = ((bk1 & 31) << 2) + 1; } }
    { int mv = bk2 & KEYMASK; if (mv < best_mv) { best_mv = mv; bi = ((bk2 & 31) << 2) + 2; } }
    { int mv = bk3 & KEYMASK; if (mv < best_mv) { best_mv = mv; bi = ((bk3 & 31) << 2) + 3; } }

    // ---- deferred per-proposal loads + direct bbox gather for chosen bi ----
    const float conf = topk_confs[(size_t)b * PP + t];
    const float* mp = match_bbox_preds + ((size_t)b * PP + t) * 2;
    const float pb0 = mp[0];
    const float pb1 = mp[1];
    const float2 mb = *(const float2*)(gt_bbox + ((size_t)b * GG + bi) * 2); // L2-hot

    // ---- exact fp32 threshold recheck for chosen bi ----
    // d2 <= 500^2  <=>  e+EOFF <= 0.5*(500^2 - cc) + EOFF
    const float cc = __fmaf_rn(cz, cz, __fmaf_rn(cy, cy, cx * cx));
    const float e_best = __fmaf_rn(cx, s_nx[bi],
                        __fmaf_rn(cy, s_ny[bi],
                        __fmaf_rn(cz, s_nz[bi], s_h[bi])));
    const float thresh_e = __fmaf_rn(-0.5f, cc, 0.5f * DIST_THRESH_SQ + EOFF);
    const bool matched = !(e_best > thresh_e);
    const float p2g = matched ? (float)bi : -1.0f;

    bool ow = matched && ((pb0 < mb.x - BBOX_THRESH) || (pb1 < mb.y - BBOX_THRESH));
    const float o5 = ow ? mb.x : pb0;
    const float o6 = ow ? mb.y : pb1;

    // ---- stage [P,7] tile (stride 7 -> conflict-free), float4 store ----
    float* so = (float*)s_out4 + t * 7;
    so[0] = cx; so[1] = cy; so[2] = cz;
    so[3] = p2g; so[4] = conf;
    so[5] = o5;  so[6] = o6;
    __syncthreads();

    float4* dst = (float4*)(out + (size_t)b * (PP * 7));
    #pragma unroll
    for (int i = t; i < 224; i += PP)   // 896 floats = 224 float4
        dst[i] = s_out4[i];
}

extern "C" void kernel_launch(void* const* d_in, const int* in_sizes, int n_in,
                              void* d_out, int out_size)
{
    const int*   topk_index       = (const int*)  d_in[0];
    const float* topk_confs       = (const float*)d_in[1];
    const float* match_bbox_preds = (const float*)d_in[2];
    const float* roots_3d         = (const float*)d_in[3];
    const float* gt_bbox          = (const float*)d_in[4];
    const int*   num_person       = (const int*)  d_in[5];
    float* out = (float*)d_out;

    proposal_layer_kernel<<<BB, PP>>>(topk_index, topk_confs, match_bbox_preds,
                                      roots_3d, gt_bbox, num_person, out);
}